// round 8
// baseline (speedup 1.0000x reference)
#include <cuda_runtime.h>
#include <cuda_fp16.h>
#include <cstdint>

// ===== problem constants =====
#define RTOT  32768
#define CDIM  256
#define KTOT  8192
#define MT    128
#define NT    128
#define KSTEPS 8               // 8 k-chunks of 32 (int8)
#define NUM_MT (RTOT/MT)       // 256
#define NUM_NT (KTOT/NT)       // 64
#define JOBS  (NUM_MT*NUM_NT)  // 16384
#define NCTA  148
#define THREADS 512            // 16 warps

#define SMEM_A    0
#define SMEM_B0   65536
#define SMEM_B1   131072
#define SMEM_TOTAL 196608      // A (2 img x 8 panels x 4KB) + B double buffer 2x64KB

#define IDX_OFF  8388608
#define DIST_OFF (8388608+32768)

#define VOFF 1024.0f
#define MARGIN 0.06f
#define FIXROWS 16

// quantization: x ~= a0/16 + a1/4064
#define S0F   16.0f
#define S0INV 0.0625f
#define S1F   4064.0f
#define C0    0.0078125f       // 2/(16*16)
#define C1    3.0757874e-05f   // 2/(16*4064)

// ===== device globals (static scratch) =====
__device__ uint4 g_Aimg[(size_t)NUM_MT*4096];   // [mtile][img(2)][kc(8)][256 units] swizzled int8
__device__ uint4 g_Bimg[(size_t)NUM_NT*4096];
__device__ float g_cbsq[KTOT];
__device__ float g_cbsqo[KTOT];                 // cbsq + VOFF
__device__ float g_xsq[RTOT];
__device__ int   g_idx[RTOT];
__device__ unsigned long long g_best[RTOT];
__device__ unsigned int g_best2[RTOT];
__device__ int g_fixcnt;
__device__ int g_fixrows[RTOT];

// ===== helpers =====
__device__ __forceinline__ uint32_t smem_u32(const void* p) {
    uint32_t a;
    asm("{ .reg .u64 t; cvta.to.shared.u64 t, %1; cvt.u32.u64 %0, t; }" : "=r"(a) : "l"(p));
    return a;
}
__device__ __forceinline__ void cp_async16(uint32_t sa, const void* g) {
    asm volatile("cp.async.cg.shared.global [%0], [%1], 16;" :: "r"(sa), "l"(g));
}
#define CP_COMMIT() asm volatile("cp.async.commit_group;" ::: "memory")
#define CP_WAIT(N)  asm volatile("cp.async.wait_group %0;" :: "n"(N) : "memory")

__device__ __forceinline__ void ldsm4(uint32_t* r, uint32_t addr) {
    asm volatile("ldmatrix.sync.aligned.m8n8.x4.shared.b16 {%0,%1,%2,%3}, [%4];"
        : "=r"(r[0]), "=r"(r[1]), "=r"(r[2]), "=r"(r[3]) : "r"(addr));
}
__device__ __forceinline__ void imma16832(int* c, const uint32_t* a, uint32_t b0, uint32_t b1) {
    asm volatile("mma.sync.aligned.m16n8k32.row.col.s32.s8.s8.s32 "
        "{%0,%1,%2,%3}, {%4,%5,%6,%7}, {%8,%9}, {%0,%1,%2,%3};"
        : "+r"(c[0]), "+r"(c[1]), "+r"(c[2]), "+r"(c[3])
        : "r"(a[0]), "r"(a[1]), "r"(a[2]), "r"(a[3]), "r"(b0), "r"(b1));
}
__device__ __forceinline__ uint32_t encf(float f) {
    uint32_t u = __float_as_uint(f);
    return (u & 0x80000000u) ? ~u : (u | 0x80000000u);
}
__device__ __forceinline__ float decf(uint32_t e) {
    uint32_t u = (e & 0x80000000u) ? (e & 0x7fffffffu) : ~e;
    return __uint_as_float(u);
}

// ===== small kernels =====
__global__ void init_kernel() {
    int i = blockIdx.x * 256 + threadIdx.x;
    g_best[i] = ~0ull;
    g_best2[i] = 0xFFFFFFFFu;
    if (i == 0) g_fixcnt = 0;
}

__global__ void rowsq_kernel(const float* __restrict__ in, int rows, int which) {
    int gw = (blockIdx.x * blockDim.x + threadIdx.x) >> 5;
    int lane = threadIdx.x & 31;
    if (gw >= rows) return;
    const float4* p = reinterpret_cast<const float4*>(in) + (size_t)gw * (CDIM / 4);
    float s = 0.f;
#pragma unroll
    for (int k = 0; k < 2; ++k) {
        float4 v = p[lane + 32 * k];
        s += v.x*v.x + v.y*v.y + v.z*v.z + v.w*v.w;
    }
#pragma unroll
    for (int o = 16; o; o >>= 1) s += __shfl_xor_sync(0xffffffffu, s, o);
    if (lane == 0) {
        if (which == 0) g_xsq[gw] = s;
        else { g_cbsq[gw] = s; g_cbsqo[gw] = s + VOFF; }
    }
}

// int8 dual-image pre-swizzled panels: img0 = a0 = rint(16x); img1 = a1 = rint(4064*(x-a0/16))
__device__ __forceinline__ void prep_unit(const float* __restrict__ src, int t, uint4* img) {
    int row = t >> 5, u = t & 31;
    int kc = u >> 2, kh = (u >> 1) & 1, im = u & 1;
    const float* r = src + (size_t)row * CDIM + kc * 32 + kh * 16;
    uint32_t wds[4];
#pragma unroll
    for (int wq = 0; wq < 4; ++wq) {
        uint32_t acc = 0;
#pragma unroll
        for (int b = 0; b < 4; ++b) {
            float v = r[wq * 4 + b];
            float a0 = rintf(v * S0F);
            float q;
            if (im == 0) q = a0;
            else         q = rintf(fmaf(a0, -S0INV, v) * S1F);
            int qi = (int)q;
            acc |= ((uint32_t)qi & 0xFFu) << (b * 8);
        }
        wds[wq] = acc;
    }
    uint4 val; val.x = wds[0]; val.y = wds[1]; val.z = wds[2]; val.w = wds[3];
    int tile = row >> 7, rl = row & 127;
    int phys = (rl * 2 + kh) ^ ((rl >> 2) & 1);
    img[(size_t)tile * 4096 + (im * 8 + kc) * 256 + phys] = val;
}

__global__ void prep_a_kernel(const float* __restrict__ x) {
    prep_unit(x, blockIdx.x * 256 + threadIdx.x, g_Aimg);
}
__global__ void prep_b_kernel(const float* __restrict__ cb) {
    prep_unit(cb, blockIdx.x * 256 + threadIdx.x, g_Bimg);
}

// ===== main IMMA kernel (512 threads) =====
__device__ __forceinline__ void issue_Bjob(uint32_t smemB, int nt, int tid) {
    const uint4* src = g_Bimg + (size_t)nt * 4096 + tid;
#pragma unroll
    for (int i = 0; i < 8; ++i)
        cp_async16(smemB + (tid + i * 512) * 16, src + i * 512);
}
__device__ __forceinline__ void issue_A(uint32_t smemA, int m, int tid) {
    const uint4* src = g_Aimg + (size_t)m * 4096 + tid;
#pragma unroll
    for (int i = 0; i < 8; ++i)
        cp_async16(smemA + (tid + i * 512) * 16, src + i * 512);
}

__global__ __launch_bounds__(THREADS, 1)
void vq_imma_kernel() {
    extern __shared__ char smem[];
    uint32_t sb = smem_u32(smem);
    uint32_t smA = sb + SMEM_A;
    uint32_t smB[2] = { sb + SMEM_B0, sb + SMEM_B1 };

    int tid = threadIdx.x;
    int l = tid & 31, w = tid >> 5;
    int wm = w >> 1, wn = w & 1;      // wm: 8 row-slices of 16; wn: 2 col-halves of 64

    // ldmatrix lane maps (x4, matrices: m = l>>3; m&1 selects row/code +8; m>>1 selects k-half)
    uint32_t aoff, boff;
    {
        int mI = l >> 3, r = l & 7;
        int arow = wm * 16 + (mI & 1) * 8 + r;
        int akh = mI >> 1;
        aoff = (uint32_t)(((arow * 2 + akh) ^ ((arow >> 2) & 1)) << 4);
        int code = wn * 64 + (mI & 1) * 8 + r;   // group 0; group g adds 512 bytes
        boff = (uint32_t)(((code * 2 + akh) ^ ((code >> 2) & 1)) << 4);
    }

    int start = (int)(((long long)blockIdx.x * JOBS) / NCTA);
    int end   = (int)(((long long)(blockIdx.x + 1) * JOBS) / NCTA);

    int cur_m = start >> 6;
    issue_A(smA, cur_m, tid); CP_COMMIT();
    issue_Bjob(smB[0], start & 63, tid); CP_COMMIT();
    CP_WAIT(0);
    __syncthreads();
    int buf = 0;

    // running per-row argmin state, indexed [h]; values offset by VOFF
    float rb[2] = {3.4e38f, 3.4e38f};
    float rs[2] = {3.4e38f, 3.4e38f};
    int   ri[2] = {0, 0};

    for (int j = start; j < end; ++j) {
        int ntj = j & 63;
        int jn = j + 1;
        bool nx_same = (jn < end) && ((jn >> 6) == cur_m);

        // prefetch next job's B into the other buffer (overlaps full job)
        if (nx_same) { issue_Bjob(smB[buf ^ 1], jn & 63, tid); CP_COMMIT(); }

        int acc0[8][4], acc1[8][4];
#pragma unroll
        for (int nb = 0; nb < 8; ++nb)
#pragma unroll
            for (int q = 0; q < 4; ++q) { acc0[nb][q] = 0; acc1[nb][q] = 0; }

        uint32_t Bbase = smB[buf];
#pragma unroll
        for (int ks = 0; ks < KSTEPS; ++ks) {
            uint32_t A0p = smA + ks * 4096;
            uint32_t B0p = Bbase + ks * 4096;
            uint32_t af0[4], af1[4];
            ldsm4(af0, A0p + aoff);
            ldsm4(af1, A0p + 32768 + aoff);
#pragma unroll
            for (int g = 0; g < 4; ++g) {
                uint32_t b0[4], b1[4];
                ldsm4(b0, B0p + boff + g * 512);
                ldsm4(b1, B0p + 32768 + boff + g * 512);
                imma16832(acc0[g*2  ], af0, b0[0], b0[2]);
                imma16832(acc0[g*2+1], af0, b0[1], b0[3]);
                imma16832(acc1[g*2  ], af0, b1[0], b1[2]);
                imma16832(acc1[g*2+1], af0, b1[1], b1[3]);
                imma16832(acc1[g*2  ], af1, b0[0], b0[2]);
                imma16832(acc1[g*2+1], af1, b0[1], b0[3]);
            }
        }

        // ---- epilogue: val = |c|^2+VOFF - 2*dot ; packed-key min + exact second ----
        int qbase = ntj * 128 + wn * 64 + (l & 3) * 2;
        float qv[16];
#pragma unroll
        for (int nb = 0; nb < 8; ++nb) {
            qv[nb * 2]     = __ldg(&g_cbsqo[qbase + nb * 8]);
            qv[nb * 2 + 1] = __ldg(&g_cbsqo[qbase + nb * 8 + 1]);
        }
#pragma unroll
        for (int h = 0; h < 2; ++h) {
            uint32_t k1 = 0xFFFFFFFFu, k2 = 0xFFFFFFFFu;
#pragma unroll
            for (int nb = 0; nb < 8; ++nb)
#pragma unroll
                for (int c = 0; c < 2; ++c) {
                    float v = fmaf(-C0, (float)acc0[nb][h * 2 + c],
                              fmaf(-C1, (float)acc1[nb][h * 2 + c], qv[nb * 2 + c]));
                    uint32_t k = (__float_as_uint(v) & 0xFFFFFFF0u) | (uint32_t)(nb * 2 + c);
                    uint32_t t = max(k1, k);
                    k1 = min(k1, k);
                    k2 = min(k2, t);
                }
            float v1 = __uint_as_float(k1 & 0xFFFFFFF0u);
            float v2 = __uint_as_float(k2 & 0xFFFFFFF0u);
            int li = (int)(k1 & 15u);
            int gidx = qbase + (li >> 1) * 8 + (li & 1);
            if (v1 < rb[h]) {
                rs[h] = fminf(rb[h], v2);
                rb[h] = v1; ri[h] = gidx;
            } else {
                rs[h] = fminf(rs[h], v1);
            }
        }

        bool m_change = (jn < end) && !nx_same;
        if (m_change || jn == end) {
            // flush 2 rows: quad-merge then atomic dance
#pragma unroll
            for (int h = 0; h < 2; ++h) {
                float bv = rb[h], sv = rs[h];
                int bi = ri[h];
#pragma unroll
                for (int o = 1; o < 4; o <<= 1) {
                    float ov = __shfl_xor_sync(0xffffffffu, bv, o);
                    int   oi = __shfl_xor_sync(0xffffffffu, bi, o);
                    float os = __shfl_xor_sync(0xffffffffu, sv, o);
                    if (ov < bv || (ov == bv && oi < bi)) {
                        sv = fminf(bv, os); bv = ov; bi = oi;
                    } else {
                        sv = fminf(sv, ov);
                    }
                }
                if ((l & 3) == 0) {
                    int r = cur_m * MT + wm * 16 + h * 8 + (l >> 2);
                    unsigned long long key =
                        ((unsigned long long)encf(bv) << 32) | (uint32_t)bi;
                    unsigned long long old = atomicMin(&g_best[r], key);
                    uint32_t oldenc = (uint32_t)(old >> 32);
                    uint32_t be = encf(bv);
                    uint32_t cand = min(encf(sv), max(be, oldenc));
                    atomicMin(&g_best2[r], cand);
                }
                rb[h] = 3.4e38f; rs[h] = 3.4e38f; ri[h] = 0;
            }
        }

        if (nx_same) {
            CP_WAIT(0);
            __syncthreads();
            buf ^= 1;
        } else if (jn < end) {
            __syncthreads();          // all warps done reading A
            cur_m = jn >> 6;
            issue_A(smA, cur_m, tid); CP_COMMIT();
            issue_Bjob(smB[buf], jn & 63, tid); CP_COMMIT();
            CP_WAIT(0);
            __syncthreads();
        }
    }
}

// ===== finalize: decode, flag rows with small approx gap =====
__global__ void final_kernel(float* __restrict__ out) {
    int i = blockIdx.x * 256 + threadIdx.x;
    unsigned long long key = g_best[i];
    int idx = (int)(uint32_t)key;
    float val = decf((uint32_t)(key >> 32)) - VOFF;
    float sec = decf(g_best2[i]) - VOFF;
    out[IDX_OFF + i]  = (float)idx;
    out[DIST_OFF + i] = g_xsq[i] + val;
    g_idx[i] = idx;
    if (sec - val < MARGIN) {
        int p = atomicAdd(&g_fixcnt, 1);
        g_fixrows[p] = i;
    }
}

// ===== exact fp32 rescan for flagged rows: 16 rows/block, 4x4 reg tiles =====
__global__ __launch_bounds__(256) void fixup_kernel(const float* __restrict__ x,
                                                    const float* __restrict__ cb,
                                                    float* __restrict__ out) {
    __shared__ float4 xs[FIXROWS][64];
    __shared__ unsigned long long wk[FIXROWS][2];
    int tid = threadIdx.x;
    int n = g_fixcnt;
    int ngroups = (n + FIXROWS - 1) / FIXROWS;
    const float4* c4 = reinterpret_cast<const float4*>(cb);
    for (int g = blockIdx.x; g < ngroups; g += gridDim.x) {
        __syncthreads();
        for (int i = tid; i < FIXROWS * 64; i += 256) {
            int r = i >> 6, q = i & 63;
            int fr = g * FIXROWS + r;
            int row = g_fixrows[(fr < n) ? fr : g * FIXROWS];
            xs[r][q] = reinterpret_cast<const float4*>(x)[(size_t)row * 64 + q];
        }
        __syncthreads();
        int rg = tid >> 6;            // 4 row-groups of 4 rows
        int cg = tid & 63;
        float bv[4] = {3.4e38f,3.4e38f,3.4e38f,3.4e38f};
        int   bi[4] = {0,0,0,0};
        for (int k = 0; k < 32; ++k) {
            int c0 = k * 256 + cg * 4;
            float acc[4][4];
#pragma unroll
            for (int r = 0; r < 4; ++r)
#pragma unroll
                for (int cc = 0; cc < 4; ++cc) acc[r][cc] = 0.f;
#pragma unroll 8
            for (int q = 0; q < 64; ++q) {
                float4 xv[4];
#pragma unroll
                for (int r = 0; r < 4; ++r) xv[r] = xs[rg * 4 + r][q];
#pragma unroll
                for (int cc = 0; cc < 4; ++cc) {
                    float4 v = c4[(size_t)(c0 + cc) * 64 + q];
#pragma unroll
                    for (int r = 0; r < 4; ++r) {
                        acc[r][cc] = fmaf(v.x, xv[r].x, acc[r][cc]);
                        acc[r][cc] = fmaf(v.y, xv[r].y, acc[r][cc]);
                        acc[r][cc] = fmaf(v.z, xv[r].z, acc[r][cc]);
                        acc[r][cc] = fmaf(v.w, xv[r].w, acc[r][cc]);
                    }
                }
            }
#pragma unroll
            for (int cc = 0; cc < 4; ++cc) {
                float cq = __ldg(&g_cbsq[c0 + cc]);
#pragma unroll
                for (int r = 0; r < 4; ++r) {
                    float val = fmaf(-2.f, acc[r][cc], cq);
                    if (val < bv[r] || (val == bv[r] && c0 + cc < bi[r])) {
                        bv[r] = val; bi[r] = c0 + cc;
                    }
                }
            }
        }
#pragma unroll
        for (int r = 0; r < 4; ++r) {
            unsigned long long key =
                ((unsigned long long)encf(bv[r]) << 32) | (uint32_t)bi[r];
#pragma unroll
            for (int o = 16; o; o >>= 1) {
                unsigned long long ok = __shfl_xor_sync(0xffffffffu, key, o);
                key = min(key, ok);
            }
            if ((tid & 31) == 0) wk[rg * 4 + r][(tid >> 5) & 1] = key;
        }
        __syncthreads();
        if (tid < FIXROWS) {
            int fr = g * FIXROWS + tid;
            if (fr < n) {
                unsigned long long best = min(wk[tid][0], wk[tid][1]);
                int row = g_fixrows[fr];
                int idx = (int)(uint32_t)best;
                out[IDX_OFF + row]  = (float)idx;
                out[DIST_OFF + row] = g_xsq[row] + decf((uint32_t)(best >> 32));
                g_idx[row] = idx;
            }
        }
    }
}

// ===== gather codes =====
__global__ void gather_kernel(const float* __restrict__ cb, float* __restrict__ out) {
    int tid = threadIdx.x;
    int row = blockIdx.x * 4 + (tid >> 6);
    int c = tid & 63;
    int idx = g_idx[row];
    reinterpret_cast<float4*>(out)[(size_t)row * 64 + c] =
        reinterpret_cast<const float4*>(cb)[(size_t)idx * 64 + c];
}

extern "C" void kernel_launch(void* const* d_in, const int* in_sizes, int n_in,
                              void* d_out, int out_size) {
    const float* x  = (const float*)d_in[0];   // z_e_x  [8,4096,256] f32
    const float* cb = (const float*)d_in[1];   // codebook [8192,256] f32
    float* out = (float*)d_out;                // codes | idx | distances (f32)

    cudaFuncSetAttribute(vq_imma_kernel,
                         cudaFuncAttributeMaxDynamicSharedMemorySize, SMEM_TOTAL);

    init_kernel<<<RTOT / 256, 256>>>();
    rowsq_kernel<<<(RTOT * 32) / 256, 256>>>(x, RTOT, 0);
    rowsq_kernel<<<(KTOT * 32) / 256, 256>>>(cb, KTOT, 1);
    prep_a_kernel<<<(RTOT * 32) / 256, 256>>>(x);
    prep_b_kernel<<<(KTOT * 32) / 256, 256>>>(cb);
    vq_imma_kernel<<<NCTA, THREADS, SMEM_TOTAL>>>();
    final_kernel<<<RTOT / 256, 256>>>(out);
    fixup_kernel<<<NCTA, 256>>>(x, cb, out);
    gather_kernel<<<RTOT / 4, 256>>>(cb, out);
}

// round 9
// speedup vs baseline: 2.6347x; 2.6347x over previous
#include <cuda_runtime.h>
#include <cuda_fp16.h>
#include <cstdint>

// ===== problem constants =====
#define RTOT  32768
#define CDIM  256
#define KTOT  8192
#define MT    128
#define NT    128
#define KSTEPS 16              // single product: hi*hi
#define NUM_MT (RTOT/MT)       // 256
#define NUM_NT (KTOT/NT)       // 64
#define JOBS  (NUM_MT*NUM_NT)  // 16384
#define NCTA  148
#define THREADS 256

#define SMEM_A    0
#define SMEM_B0   65536
#define SMEM_B1   131072
#define SMEM_TOTAL 196608      // A 64KB + B double buffer 2x64KB

#define IDX_OFF  8388608
#define DIST_OFF (8388608+32768)

#define VOFF 1024.0f
#define MARGIN 0.09f
#define FIXROWS 16

// ===== device globals (static scratch) =====
__device__ uint4 g_Aimg[(size_t)NUM_MT*4096];   // 16MB: [mtile][panel(16)][256 units] swizzled hi-fp16
__device__ uint4 g_Bimg[(size_t)NUM_NT*4096];   // 4MB
__device__ float g_cbsq[KTOT];
__device__ float g_cbsqo[KTOT];                 // cbsq + VOFF
__device__ float g_xsq[RTOT];
__device__ int   g_idx[RTOT];
__device__ unsigned long long g_best[RTOT];
__device__ unsigned int g_best2[RTOT];
__device__ int g_fixcnt;
__device__ int g_fixrows[RTOT];

// ===== helpers =====
__device__ __forceinline__ uint32_t smem_u32(const void* p) {
    uint32_t a;
    asm("{ .reg .u64 t; cvta.to.shared.u64 t, %1; cvt.u32.u64 %0, t; }" : "=r"(a) : "l"(p));
    return a;
}
__device__ __forceinline__ void cp_async16(uint32_t sa, const void* g) {
    asm volatile("cp.async.cg.shared.global [%0], [%1], 16;" :: "r"(sa), "l"(g));
}
#define CP_COMMIT() asm volatile("cp.async.commit_group;" ::: "memory")
#define CP_WAIT(N)  asm volatile("cp.async.wait_group %0;" :: "n"(N) : "memory")

__device__ __forceinline__ void ldsm4(uint32_t* r, uint32_t addr) {
    asm volatile("ldmatrix.sync.aligned.m8n8.x4.shared.b16 {%0,%1,%2,%3}, [%4];"
        : "=r"(r[0]), "=r"(r[1]), "=r"(r[2]), "=r"(r[3]) : "r"(addr));
}
__device__ __forceinline__ void mma16816(float* c, const uint32_t* a, uint32_t b0, uint32_t b1) {
    asm volatile("mma.sync.aligned.m16n8k16.row.col.f32.f16.f16.f32 "
        "{%0,%1,%2,%3}, {%4,%5,%6,%7}, {%8,%9}, {%0,%1,%2,%3};"
        : "+f"(c[0]), "+f"(c[1]), "+f"(c[2]), "+f"(c[3])
        : "r"(a[0]), "r"(a[1]), "r"(a[2]), "r"(a[3]), "r"(b0), "r"(b1));
}
__device__ __forceinline__ uint32_t encf(float f) {
    uint32_t u = __float_as_uint(f);
    return (u & 0x80000000u) ? ~u : (u | 0x80000000u);
}
__device__ __forceinline__ float decf(uint32_t e) {
    uint32_t u = (e & 0x80000000u) ? (e & 0x7fffffffu) : ~e;
    return __uint_as_float(u);
}
__device__ __forceinline__ uint32_t packh2(__half a, __half b) {
    __half2 h = __halves2half2(a, b);
    return *reinterpret_cast<uint32_t*>(&h);
}

// ===== launch #1: init best/second/fixcnt =====
__global__ void init_kernel() {
    int i = blockIdx.x * 256 + threadIdx.x;
    g_best[i] = ~0ull;
    g_best2[i] = 0xFFFFFFFFu;
    if (i == 0) g_fixcnt = 0;
}

// ===== launches #2/#3: prep (fp16 swizzled image + fused row sum-of-squares) =====
// 32 consecutive threads own one row (warp-aligned groups); each reads 8 floats.
__device__ __forceinline__ float prep_unit(const float* __restrict__ src, int t, uint4* img) {
    int row = t >> 5, u = t & 31;
    int ks = u >> 1, kh = u & 1;
    int kext = ks * 16 + kh * 8;
    const float* r = src + (size_t)row * CDIM;
    float s = 0.f;
    __half h[8];
#pragma unroll
    for (int i = 0; i < 8; ++i) {
        float v = r[kext + i];
        s = fmaf(v, v, s);
        h[i] = __float2half(v);
    }
    uint4 val;
    val.x = packh2(h[0], h[1]); val.y = packh2(h[2], h[3]);
    val.z = packh2(h[4], h[5]); val.w = packh2(h[6], h[7]);
    int tile = row >> 7, rl = row & 127;
    int phys = (rl * 2 + kh) ^ ((rl >> 2) & 1);
    img[(size_t)tile * 4096 + ks * 256 + phys] = val;
    // warp-group reduce (32 lanes == one row)
#pragma unroll
    for (int o = 16; o; o >>= 1) s += __shfl_xor_sync(0xffffffffu, s, o);
    return s;
}

__global__ void prep_a_kernel(const float* __restrict__ x) {
    int t = blockIdx.x * 256 + threadIdx.x;
    float s = prep_unit(x, t, g_Aimg);
    if ((t & 31) == 0) g_xsq[t >> 5] = s;
}
__global__ void prep_b_kernel(const float* __restrict__ cb) {
    int t = blockIdx.x * 256 + threadIdx.x;
    float s = prep_unit(cb, t, g_Bimg);
    if ((t & 31) == 0) { g_cbsq[t >> 5] = s; g_cbsqo[t >> 5] = s + VOFF; }
}

// ===== launch #4: main HMMA kernel (R6 config, unchanged) =====
__device__ __forceinline__ void issue_Bjob(uint32_t smemB, int nt, int tid) {
    const uint4* src = g_Bimg + (size_t)nt * 4096 + tid;
#pragma unroll
    for (int i = 0; i < 16; ++i)
        cp_async16(smemB + (tid + i * 256) * 16, src + i * 256);
}
__device__ __forceinline__ void issue_A(uint32_t smemA, int m, int tid) {
    const uint4* src = g_Aimg + (size_t)m * 4096 + tid;
#pragma unroll
    for (int i = 0; i < 16; ++i)
        cp_async16(smemA + (tid + i * 256) * 16, src + i * 256);
}

__global__ __launch_bounds__(THREADS, 1)
void vq_hmma_kernel() {
    extern __shared__ char smem[];
    uint32_t sb = smem_u32(smem);
    uint32_t smA = sb + SMEM_A;
    uint32_t smB[2] = { sb + SMEM_B0, sb + SMEM_B1 };

    int tid = threadIdx.x;
    int l = tid & 31, w = tid >> 5;
    int wm = w >> 1, wn = w & 1;

    uint32_t aoff[2], boff[4];
#pragma unroll
    for (int mt = 0; mt < 2; ++mt) {
        int row = wm * 32 + mt * 16 + (l & 15);
        int kh = l >> 4;
        aoff[mt] = (uint32_t)(((row * 2 + kh) ^ ((row >> 2) & 1)) << 4);
    }
#pragma unroll
    for (int nt4 = 0; nt4 < 4; ++nt4) {
        int code = wn * 64 + nt4 * 16 + (l & 7) + ((l >> 4) << 3);
        int kh = (l >> 3) & 1;
        boff[nt4] = (uint32_t)(((code * 2 + kh) ^ ((code >> 2) & 1)) << 4);
    }

    int start = (int)(((long long)blockIdx.x * JOBS) / NCTA);
    int end   = (int)(((long long)(blockIdx.x + 1) * JOBS) / NCTA);

    int cur_m = start >> 6;
    issue_A(smA, cur_m, tid); CP_COMMIT();
    issue_Bjob(smB[0], start & 63, tid); CP_COMMIT();
    CP_WAIT(0);
    __syncthreads();
    int buf = 0;

    float rb[2][2] = {{3.4e38f,3.4e38f},{3.4e38f,3.4e38f}};
    float rs[2][2] = {{3.4e38f,3.4e38f},{3.4e38f,3.4e38f}};
    int   ri[2][2] = {{0,0},{0,0}};

    for (int j = start; j < end; ++j) {
        int ntj = j & 63;
        int jn = j + 1;
        bool nx_same = (jn < end) && ((jn >> 6) == cur_m);

        if (nx_same) { issue_Bjob(smB[buf ^ 1], jn & 63, tid); CP_COMMIT(); }

        float qv[16];
        int qbase = ntj * 128 + wn * 64 + (l & 3) * 2;
#pragma unroll
        for (int nb = 0; nb < 8; ++nb) {
            qv[nb * 2]     = __ldg(&g_cbsqo[qbase + nb * 8]);
            qv[nb * 2 + 1] = __ldg(&g_cbsqo[qbase + nb * 8 + 1]);
        }

        float acc[2][8][4];
#pragma unroll
        for (int mt = 0; mt < 2; ++mt)
#pragma unroll
            for (int nb = 0; nb < 8; ++nb)
#pragma unroll
                for (int q = 0; q < 4; ++q) acc[mt][nb][q] = 0.f;

        uint32_t Bbase = smB[buf];
#pragma unroll
        for (int ks = 0; ks < KSTEPS; ++ks) {
            uint32_t Apan = smA + ks * 4096;
            uint32_t Bpan = Bbase + ks * 4096;
            uint32_t af[2][4], bf[4][4];
            ldsm4(af[0], Apan + aoff[0]);
            ldsm4(af[1], Apan + aoff[1]);
#pragma unroll
            for (int nt4 = 0; nt4 < 4; ++nt4) ldsm4(bf[nt4], Bpan + boff[nt4]);
#pragma unroll
            for (int mt = 0; mt < 2; ++mt)
#pragma unroll
                for (int nt4 = 0; nt4 < 4; ++nt4) {
                    mma16816(acc[mt][nt4*2  ], af[mt], bf[nt4][0], bf[nt4][1]);
                    mma16816(acc[mt][nt4*2+1], af[mt], bf[nt4][2], bf[nt4][3]);
                }
        }

        // epilogue: packed-key min + exact second, branchless
#pragma unroll
        for (int mt = 0; mt < 2; ++mt)
#pragma unroll
            for (int h = 0; h < 2; ++h) {
                uint32_t k1 = 0xFFFFFFFFu, k2 = 0xFFFFFFFFu;
#pragma unroll
                for (int nb = 0; nb < 8; ++nb)
#pragma unroll
                    for (int c = 0; c < 2; ++c) {
                        float v = fmaf(-2.f, acc[mt][nb][h * 2 + c], qv[nb * 2 + c]);
                        uint32_t k = (__float_as_uint(v) & 0xFFFFFFF0u) | (uint32_t)(nb * 2 + c);
                        uint32_t t = max(k1, k);
                        k1 = min(k1, k);
                        k2 = min(k2, t);
                    }
                float v1 = __uint_as_float(k1 & 0xFFFFFFF0u);
                float v2 = __uint_as_float(k2 & 0xFFFFFFF0u);
                int li = (int)(k1 & 15u);
                int gidx = qbase + (li >> 1) * 8 + (li & 1);
                if (v1 < rb[mt][h]) {
                    rs[mt][h] = fminf(rb[mt][h], v2);
                    rb[mt][h] = v1; ri[mt][h] = gidx;
                } else {
                    rs[mt][h] = fminf(rs[mt][h], v1);
                }
            }

        bool m_change = (jn < end) && !nx_same;
        if (m_change || jn == end) {
#pragma unroll
            for (int mt = 0; mt < 2; ++mt)
#pragma unroll
                for (int h = 0; h < 2; ++h) {
                    float bv = rb[mt][h], sv = rs[mt][h];
                    int bi = ri[mt][h];
#pragma unroll
                    for (int o = 1; o < 4; o <<= 1) {
                        float ov = __shfl_xor_sync(0xffffffffu, bv, o);
                        int   oi = __shfl_xor_sync(0xffffffffu, bi, o);
                        float os = __shfl_xor_sync(0xffffffffu, sv, o);
                        if (ov < bv || (ov == bv && oi < bi)) {
                            sv = fminf(bv, os); bv = ov; bi = oi;
                        } else {
                            sv = fminf(sv, ov);
                        }
                    }
                    if ((l & 3) == 0) {
                        int r = cur_m * MT + wm * 32 + mt * 16 + h * 8 + (l >> 2);
                        unsigned long long key =
                            ((unsigned long long)encf(bv) << 32) | (uint32_t)bi;
                        unsigned long long old = atomicMin(&g_best[r], key);
                        uint32_t oldenc = (uint32_t)(old >> 32);
                        uint32_t be = encf(bv);
                        uint32_t cand = min(encf(sv), max(be, oldenc));
                        atomicMin(&g_best2[r], cand);
                    }
                    rb[mt][h] = 3.4e38f; rs[mt][h] = 3.4e38f; ri[mt][h] = 0;
                }
        }

        if (nx_same) {
            CP_WAIT(0);
            __syncthreads();
            buf ^= 1;
        } else if (jn < end) {
            __syncthreads();
            cur_m = jn >> 6;
            issue_A(smA, cur_m, tid); CP_COMMIT();
            issue_Bjob(smB[buf], jn & 63, tid); CP_COMMIT();
            CP_WAIT(0);
            __syncthreads();
        }
    }
}

// ===== launch #5: finalize, flag close rows =====
__global__ void final_kernel(float* __restrict__ out) {
    int i = blockIdx.x * 256 + threadIdx.x;
    unsigned long long key = g_best[i];
    int idx = (int)(uint32_t)key;
    float val = decf((uint32_t)(key >> 32)) - VOFF;
    float sec = decf(g_best2[i]) - VOFF;
    out[IDX_OFF + i]  = (float)idx;
    out[DIST_OFF + i] = g_xsq[i] + val;
    g_idx[i] = idx;
    if (sec - val < MARGIN) {
        int p = atomicAdd(&g_fixcnt, 1);
        g_fixrows[p] = i;
    }
}

// ===== launch #6: exact fp32 rescan for flagged rows =====
__global__ __launch_bounds__(256) void fixup_kernel(const float* __restrict__ x,
                                                    const float* __restrict__ cb,
                                                    float* __restrict__ out) {
    __shared__ float4 xs[FIXROWS][64];
    __shared__ unsigned long long wk[FIXROWS][2];
    int tid = threadIdx.x;
    int n = g_fixcnt;
    int ngroups = (n + FIXROWS - 1) / FIXROWS;
    const float4* c4 = reinterpret_cast<const float4*>(cb);
    for (int g = blockIdx.x; g < ngroups; g += gridDim.x) {
        __syncthreads();
        for (int i = tid; i < FIXROWS * 64; i += 256) {
            int r = i >> 6, q = i & 63;
            int fr = g * FIXROWS + r;
            int row = g_fixrows[(fr < n) ? fr : g * FIXROWS];
            xs[r][q] = reinterpret_cast<const float4*>(x)[(size_t)row * 64 + q];
        }
        __syncthreads();
        int rg = tid >> 6;
        int cg = tid & 63;
        float bv[4] = {3.4e38f,3.4e38f,3.4e38f,3.4e38f};
        int   bi[4] = {0,0,0,0};
        for (int k = 0; k < 32; ++k) {
            int c0 = k * 256 + cg * 4;
            float acc[4][4];
#pragma unroll
            for (int r = 0; r < 4; ++r)
#pragma unroll
                for (int cc = 0; cc < 4; ++cc) acc[r][cc] = 0.f;
#pragma unroll 8
            for (int q = 0; q < 64; ++q) {
                float4 xv[4];
#pragma unroll
                for (int r = 0; r < 4; ++r) xv[r] = xs[rg * 4 + r][q];
#pragma unroll
                for (int cc = 0; cc < 4; ++cc) {
                    float4 v = c4[(size_t)(c0 + cc) * 64 + q];
#pragma unroll
                    for (int r = 0; r < 4; ++r) {
                        acc[r][cc] = fmaf(v.x, xv[r].x, acc[r][cc]);
                        acc[r][cc] = fmaf(v.y, xv[r].y, acc[r][cc]);
                        acc[r][cc] = fmaf(v.z, xv[r].z, acc[r][cc]);
                        acc[r][cc] = fmaf(v.w, xv[r].w, acc[r][cc]);
                    }
                }
            }
#pragma unroll
            for (int cc = 0; cc < 4; ++cc) {
                float cq = __ldg(&g_cbsq[c0 + cc]);
#pragma unroll
                for (int r = 0; r < 4; ++r) {
                    float val = fmaf(-2.f, acc[r][cc], cq);
                    if (val < bv[r] || (val == bv[r] && c0 + cc < bi[r])) {
                        bv[r] = val; bi[r] = c0 + cc;
                    }
                }
            }
        }
#pragma unroll
        for (int r = 0; r < 4; ++r) {
            unsigned long long key =
                ((unsigned long long)encf(bv[r]) << 32) | (uint32_t)bi[r];
#pragma unroll
            for (int o = 16; o; o >>= 1) {
                unsigned long long ok = __shfl_xor_sync(0xffffffffu, key, o);
                key = min(key, ok);
            }
            if ((tid & 31) == 0) wk[rg * 4 + r][(tid >> 5) & 1] = key;
        }
        __syncthreads();
        if (tid < FIXROWS) {
            int fr = g * FIXROWS + tid;
            if (fr < n) {
                unsigned long long best = min(wk[tid][0], wk[tid][1]);
                int row = g_fixrows[fr];
                int idx = (int)(uint32_t)best;
                out[IDX_OFF + row]  = (float)idx;
                out[DIST_OFF + row] = g_xsq[row] + decf((uint32_t)(best >> 32));
                g_idx[row] = idx;
            }
        }
    }
}

// ===== launch #7: gather codes =====
__global__ void gather_kernel(const float* __restrict__ cb, float* __restrict__ out) {
    int tid = threadIdx.x;
    int row = blockIdx.x * 4 + (tid >> 6);
    int c = tid & 63;
    int idx = g_idx[row];
    reinterpret_cast<float4*>(out)[(size_t)row * 64 + c] =
        reinterpret_cast<const float4*>(cb)[(size_t)idx * 64 + c];
}

extern "C" void kernel_launch(void* const* d_in, const int* in_sizes, int n_in,
                              void* d_out, int out_size) {
    const float* x  = (const float*)d_in[0];   // z_e_x  [8,4096,256] f32
    const float* cb = (const float*)d_in[1];   // codebook [8192,256] f32
    float* out = (float*)d_out;                // codes | idx | distances (f32)

    cudaFuncSetAttribute(vq_hmma_kernel,
                         cudaFuncAttributeMaxDynamicSharedMemorySize, SMEM_TOTAL);

    init_kernel<<<RTOT / 256, 256>>>();                    // #1
    prep_a_kernel<<<(RTOT * 32) / 256, 256>>>(x);          // #2 (+ xsq fused)
    prep_b_kernel<<<(KTOT * 32) / 256, 256>>>(cb);         // #3 (+ cbsq fused)
    vq_hmma_kernel<<<NCTA, THREADS, SMEM_TOTAL>>>();       // #4  <- ncu capture slot
    final_kernel<<<RTOT / 256, 256>>>(out);                // #5
    fixup_kernel<<<NCTA, 256>>>(x, cb, out);               // #6
    gather_kernel<<<RTOT / 4, 256>>>(cb, out);             // #7
}

// round 10
// speedup vs baseline: 5.6851x; 2.1578x over previous
#include <cuda_runtime.h>
#include <cuda_fp16.h>
#include <cstdint>

// ===== problem constants =====
#define RTOT  32768
#define CDIM  256
#define KTOT  8192
#define MT    128
#define NT    128
#define KSTEPS 16              // single product: hi*hi
#define NUM_MT (RTOT/MT)       // 256
#define NUM_NT (KTOT/NT)       // 64
#define JOBS  (NUM_MT*NUM_NT)  // 16384
#define NCTA  148
#define THREADS 256

#define SMEM_A    0
#define SMEM_B0   65536
#define SMEM_B1   131072
#define SMEM_TOTAL 196608      // A 64KB + B double buffer 2x64KB

#define IDX_OFF  8388608
#define DIST_OFF (8388608+32768)

#define VOFF 1024.0f
#define MARGIN 0.09f
#define FIXROWS 16
#define KSLICES 8              // fixup K-parallelism

// ===== device globals (static scratch) =====
__device__ uint4 g_Aimg[(size_t)NUM_MT*4096];   // 16MB: [mtile][panel(16)][256 units] swizzled hi-fp16
__device__ uint4 g_Bimg[(size_t)NUM_NT*4096];   // 4MB
__device__ float g_cbsq[KTOT];
__device__ float g_cbsqo[KTOT];                 // cbsq + VOFF
__device__ float g_xsq[RTOT];
__device__ int   g_idx[RTOT];
__device__ unsigned long long g_best[RTOT];
__device__ unsigned int g_best2[RTOT];
__device__ int g_fixcnt;
__device__ int g_fixrows[RTOT];
__device__ int g_isfix[RTOT];
__device__ unsigned long long g_fbest[RTOT];    // exact keys from fixup slices

// ===== helpers =====
__device__ __forceinline__ uint32_t smem_u32(const void* p) {
    uint32_t a;
    asm("{ .reg .u64 t; cvta.to.shared.u64 t, %1; cvt.u32.u64 %0, t; }" : "=r"(a) : "l"(p));
    return a;
}
__device__ __forceinline__ void cp_async16(uint32_t sa, const void* g) {
    asm volatile("cp.async.cg.shared.global [%0], [%1], 16;" :: "r"(sa), "l"(g));
}
#define CP_COMMIT() asm volatile("cp.async.commit_group;" ::: "memory")
#define CP_WAIT(N)  asm volatile("cp.async.wait_group %0;" :: "n"(N) : "memory")

__device__ __forceinline__ void ldsm4(uint32_t* r, uint32_t addr) {
    asm volatile("ldmatrix.sync.aligned.m8n8.x4.shared.b16 {%0,%1,%2,%3}, [%4];"
        : "=r"(r[0]), "=r"(r[1]), "=r"(r[2]), "=r"(r[3]) : "r"(addr));
}
__device__ __forceinline__ void mma16816(float* c, const uint32_t* a, uint32_t b0, uint32_t b1) {
    asm volatile("mma.sync.aligned.m16n8k16.row.col.f32.f16.f16.f32 "
        "{%0,%1,%2,%3}, {%4,%5,%6,%7}, {%8,%9}, {%0,%1,%2,%3};"
        : "+f"(c[0]), "+f"(c[1]), "+f"(c[2]), "+f"(c[3])
        : "r"(a[0]), "r"(a[1]), "r"(a[2]), "r"(a[3]), "r"(b0), "r"(b1));
}
__device__ __forceinline__ uint32_t encf(float f) {
    uint32_t u = __float_as_uint(f);
    return (u & 0x80000000u) ? ~u : (u | 0x80000000u);
}
__device__ __forceinline__ float decf(uint32_t e) {
    uint32_t u = (e & 0x80000000u) ? (e & 0x7fffffffu) : ~e;
    return __uint_as_float(u);
}
__device__ __forceinline__ uint32_t packh2(__half a, __half b) {
    __half2 h = __halves2half2(a, b);
    return *reinterpret_cast<uint32_t*>(&h);
}

// ===== launch #1: init =====
__global__ void init_kernel() {
    int i = blockIdx.x * 256 + threadIdx.x;
    g_best[i] = ~0ull;
    g_best2[i] = 0xFFFFFFFFu;
    g_isfix[i] = 0;
    g_fbest[i] = ~0ull;
    if (i == 0) g_fixcnt = 0;
}

// ===== launches #2/#3: prep (fp16 swizzled image + fused row sum-of-squares) =====
__device__ __forceinline__ float prep_unit(const float* __restrict__ src, int t, uint4* img) {
    int row = t >> 5, u = t & 31;
    int ks = u >> 1, kh = u & 1;
    int kext = ks * 16 + kh * 8;
    const float* r = src + (size_t)row * CDIM;
    float s = 0.f;
    __half h[8];
#pragma unroll
    for (int i = 0; i < 8; ++i) {
        float v = r[kext + i];
        s = fmaf(v, v, s);
        h[i] = __float2half(v);
    }
    uint4 val;
    val.x = packh2(h[0], h[1]); val.y = packh2(h[2], h[3]);
    val.z = packh2(h[4], h[5]); val.w = packh2(h[6], h[7]);
    int tile = row >> 7, rl = row & 127;
    int phys = (rl * 2 + kh) ^ ((rl >> 2) & 1);
    img[(size_t)tile * 4096 + ks * 256 + phys] = val;
#pragma unroll
    for (int o = 16; o; o >>= 1) s += __shfl_xor_sync(0xffffffffu, s, o);
    return s;
}

__global__ void prep_a_kernel(const float* __restrict__ x) {
    int t = blockIdx.x * 256 + threadIdx.x;
    float s = prep_unit(x, t, g_Aimg);
    if ((t & 31) == 0) g_xsq[t >> 5] = s;
}
__global__ void prep_b_kernel(const float* __restrict__ cb) {
    int t = blockIdx.x * 256 + threadIdx.x;
    float s = prep_unit(cb, t, g_Bimg);
    if ((t & 31) == 0) { g_cbsq[t >> 5] = s; g_cbsqo[t >> 5] = s + VOFF; }
}

// ===== launch #4: main HMMA kernel =====
__device__ __forceinline__ void issue_Bjob(uint32_t smemB, int nt, int tid) {
    const uint4* src = g_Bimg + (size_t)nt * 4096 + tid;
#pragma unroll
    for (int i = 0; i < 16; ++i)
        cp_async16(smemB + (tid + i * 256) * 16, src + i * 256);
}
__device__ __forceinline__ void issue_A(uint32_t smemA, int m, int tid) {
    const uint4* src = g_Aimg + (size_t)m * 4096 + tid;
#pragma unroll
    for (int i = 0; i < 16; ++i)
        cp_async16(smemA + (tid + i * 256) * 16, src + i * 256);
}

__global__ __launch_bounds__(THREADS, 1)
void vq_hmma_kernel() {
    extern __shared__ char smem[];
    uint32_t sb = smem_u32(smem);
    uint32_t smA = sb + SMEM_A;
    uint32_t smB[2] = { sb + SMEM_B0, sb + SMEM_B1 };

    int tid = threadIdx.x;
    int l = tid & 31, w = tid >> 5;
    int wm = w >> 1, wn = w & 1;

    uint32_t aoff[2], boff[4];
#pragma unroll
    for (int mt = 0; mt < 2; ++mt) {
        int row = wm * 32 + mt * 16 + (l & 15);
        int kh = l >> 4;
        aoff[mt] = (uint32_t)(((row * 2 + kh) ^ ((row >> 2) & 1)) << 4);
    }
#pragma unroll
    for (int nt4 = 0; nt4 < 4; ++nt4) {
        int code = wn * 64 + nt4 * 16 + (l & 7) + ((l >> 4) << 3);
        int kh = (l >> 3) & 1;
        boff[nt4] = (uint32_t)(((code * 2 + kh) ^ ((code >> 2) & 1)) << 4);
    }

    int start = (int)(((long long)blockIdx.x * JOBS) / NCTA);
    int end   = (int)(((long long)(blockIdx.x + 1) * JOBS) / NCTA);

    int cur_m = start >> 6;
    issue_A(smA, cur_m, tid); CP_COMMIT();
    issue_Bjob(smB[0], start & 63, tid); CP_COMMIT();
    CP_WAIT(0);
    __syncthreads();
    int buf = 0;

    float rb[2][2] = {{3.4e38f,3.4e38f},{3.4e38f,3.4e38f}};
    float rs[2][2] = {{3.4e38f,3.4e38f},{3.4e38f,3.4e38f}};
    int   ri[2][2] = {{0,0},{0,0}};

    for (int j = start; j < end; ++j) {
        int ntj = j & 63;
        int jn = j + 1;
        bool nx_same = (jn < end) && ((jn >> 6) == cur_m);
        bool m_change = (jn < end) && !nx_same;

        if (nx_same) { issue_Bjob(smB[buf ^ 1], jn & 63, tid); CP_COMMIT(); }

        float qv[16];
        int qbase = ntj * 128 + wn * 64 + (l & 3) * 2;
#pragma unroll
        for (int nb = 0; nb < 8; ++nb) {
            qv[nb * 2]     = __ldg(&g_cbsqo[qbase + nb * 8]);
            qv[nb * 2 + 1] = __ldg(&g_cbsqo[qbase + nb * 8 + 1]);
        }

        float acc[2][8][4];
#pragma unroll
        for (int mt = 0; mt < 2; ++mt)
#pragma unroll
            for (int nb = 0; nb < 8; ++nb)
#pragma unroll
                for (int q = 0; q < 4; ++q) acc[mt][nb][q] = 0.f;

        uint32_t Bbase = smB[buf];
#pragma unroll
        for (int ks = 0; ks < KSTEPS; ++ks) {
            uint32_t Apan = smA + ks * 4096;
            uint32_t Bpan = Bbase + ks * 4096;
            uint32_t af[2][4], bf[4][4];
            ldsm4(af[0], Apan + aoff[0]);
            ldsm4(af[1], Apan + aoff[1]);
#pragma unroll
            for (int nt4 = 0; nt4 < 4; ++nt4) ldsm4(bf[nt4], Bpan + boff[nt4]);
#pragma unroll
            for (int mt = 0; mt < 2; ++mt)
#pragma unroll
                for (int nt4 = 0; nt4 < 4; ++nt4) {
                    mma16816(acc[mt][nt4*2  ], af[mt], bf[nt4][0], bf[nt4][1]);
                    mma16816(acc[mt][nt4*2+1], af[mt], bf[nt4][2], bf[nt4][3]);
                }
        }

        // ---- buffer management BEFORE epilogue: lets one warp's epilogue
        //      overlap other warps' next-job MMAs ----
        if (nx_same) {
            CP_WAIT(0);
            __syncthreads();       // all warps done with mainloop reads of old buf
            buf ^= 1;
        } else if (m_change) {
            __syncthreads();       // all warps done reading smA
            issue_A(smA, jn >> 6, tid); CP_COMMIT();
            issue_Bjob(smB[buf], jn & 63, tid); CP_COMMIT();
        }

        // epilogue: packed-key min + exact second, branchless (registers only)
#pragma unroll
        for (int mt = 0; mt < 2; ++mt)
#pragma unroll
            for (int h = 0; h < 2; ++h) {
                uint32_t k1 = 0xFFFFFFFFu, k2 = 0xFFFFFFFFu;
#pragma unroll
                for (int nb = 0; nb < 8; ++nb)
#pragma unroll
                    for (int c = 0; c < 2; ++c) {
                        float v = fmaf(-2.f, acc[mt][nb][h * 2 + c], qv[nb * 2 + c]);
                        uint32_t k = (__float_as_uint(v) & 0xFFFFFFF0u) | (uint32_t)(nb * 2 + c);
                        uint32_t t = max(k1, k);
                        k1 = min(k1, k);
                        k2 = min(k2, t);
                    }
                float v1 = __uint_as_float(k1 & 0xFFFFFFF0u);
                float v2 = __uint_as_float(k2 & 0xFFFFFFF0u);
                int li = (int)(k1 & 15u);
                int gidx = qbase + (li >> 1) * 8 + (li & 1);
                if (v1 < rb[mt][h]) {
                    rs[mt][h] = fminf(rb[mt][h], v2);
                    rb[mt][h] = v1; ri[mt][h] = gidx;
                } else {
                    rs[mt][h] = fminf(rs[mt][h], v1);
                }
            }

        if (m_change || jn == end) {
#pragma unroll
            for (int mt = 0; mt < 2; ++mt)
#pragma unroll
                for (int h = 0; h < 2; ++h) {
                    float bv = rb[mt][h], sv = rs[mt][h];
                    int bi = ri[mt][h];
#pragma unroll
                    for (int o = 1; o < 4; o <<= 1) {
                        float ov = __shfl_xor_sync(0xffffffffu, bv, o);
                        int   oi = __shfl_xor_sync(0xffffffffu, bi, o);
                        float os = __shfl_xor_sync(0xffffffffu, sv, o);
                        if (ov < bv || (ov == bv && oi < bi)) {
                            sv = fminf(bv, os); bv = ov; bi = oi;
                        } else {
                            sv = fminf(sv, ov);
                        }
                    }
                    if ((l & 3) == 0) {
                        int r = cur_m * MT + wm * 32 + mt * 16 + h * 8 + (l >> 2);
                        unsigned long long key =
                            ((unsigned long long)encf(bv) << 32) | (uint32_t)bi;
                        unsigned long long old = atomicMin(&g_best[r], key);
                        uint32_t oldenc = (uint32_t)(old >> 32);
                        uint32_t be = encf(bv);
                        uint32_t cand = min(encf(sv), max(be, oldenc));
                        atomicMin(&g_best2[r], cand);
                    }
                    rb[mt][h] = 3.4e38f; rs[mt][h] = 3.4e38f; ri[mt][h] = 0;
                }
        }

        if (m_change) {
            cur_m = jn >> 6;
            CP_WAIT(0);
            __syncthreads();       // new A/B resident before next mainloop
        }
    }
}

// ===== launch #5: finalize, flag close rows =====
__global__ void final_kernel(float* __restrict__ out) {
    int i = blockIdx.x * 256 + threadIdx.x;
    unsigned long long key = g_best[i];
    int idx = (int)(uint32_t)key;
    float val = decf((uint32_t)(key >> 32)) - VOFF;
    float sec = decf(g_best2[i]) - VOFF;
    out[IDX_OFF + i]  = (float)idx;
    out[DIST_OFF + i] = g_xsq[i] + val;
    g_idx[i] = idx;
    if (sec - val < MARGIN) {
        g_isfix[i] = 1;
        int p = atomicAdd(&g_fixcnt, 1);
        g_fixrows[p] = i;
    }
}

// ===== launch #6: exact fp32 rescan, K-sliced 8-way; merge via atomicMin =====
__global__ __launch_bounds__(256) void fixup_kernel(const float* __restrict__ x,
                                                    const float* __restrict__ cb) {
    __shared__ float4 xs[FIXROWS][64];
    __shared__ unsigned long long wk[FIXROWS][2];
    int tid = threadIdx.x;
    int n = g_fixcnt;
    int ngroups = (n + FIXROWS - 1) / FIXROWS;
    int slice = blockIdx.x & (KSLICES - 1);     // 1024-code slice
    int g0 = blockIdx.x >> 3;
    const float4* c4 = reinterpret_cast<const float4*>(cb);
    for (int g = g0; g < ngroups; g += NCTA) {
        __syncthreads();
        for (int i = tid; i < FIXROWS * 64; i += 256) {
            int r = i >> 6, q = i & 63;
            int fr = g * FIXROWS + r;
            int row = g_fixrows[(fr < n) ? fr : g * FIXROWS];
            xs[r][q] = reinterpret_cast<const float4*>(x)[(size_t)row * 64 + q];
        }
        __syncthreads();
        int rg = tid >> 6;
        int cg = tid & 63;
        float bv[4] = {3.4e38f,3.4e38f,3.4e38f,3.4e38f};
        int   bi[4] = {0,0,0,0};
        for (int k = slice * 4; k < slice * 4 + 4; ++k) {
            int c0 = k * 256 + cg * 4;
            float acc[4][4];
#pragma unroll
            for (int r = 0; r < 4; ++r)
#pragma unroll
                for (int cc = 0; cc < 4; ++cc) acc[r][cc] = 0.f;
#pragma unroll 8
            for (int q = 0; q < 64; ++q) {
                float4 xv[4];
#pragma unroll
                for (int r = 0; r < 4; ++r) xv[r] = xs[rg * 4 + r][q];
#pragma unroll
                for (int cc = 0; cc < 4; ++cc) {
                    float4 v = c4[(size_t)(c0 + cc) * 64 + q];
#pragma unroll
                    for (int r = 0; r < 4; ++r) {
                        acc[r][cc] = fmaf(v.x, xv[r].x, acc[r][cc]);
                        acc[r][cc] = fmaf(v.y, xv[r].y, acc[r][cc]);
                        acc[r][cc] = fmaf(v.z, xv[r].z, acc[r][cc]);
                        acc[r][cc] = fmaf(v.w, xv[r].w, acc[r][cc]);
                    }
                }
            }
#pragma unroll
            for (int cc = 0; cc < 4; ++cc) {
                float cq = __ldg(&g_cbsq[c0 + cc]);
#pragma unroll
                for (int r = 0; r < 4; ++r) {
                    float val = fmaf(-2.f, acc[r][cc], cq);
                    if (val < bv[r] || (val == bv[r] && c0 + cc < bi[r])) {
                        bv[r] = val; bi[r] = c0 + cc;
                    }
                }
            }
        }
#pragma unroll
        for (int r = 0; r < 4; ++r) {
            unsigned long long key =
                ((unsigned long long)encf(bv[r]) << 32) | (uint32_t)bi[r];
#pragma unroll
            for (int o = 16; o; o >>= 1) {
                unsigned long long ok = __shfl_xor_sync(0xffffffffu, key, o);
                key = min(key, ok);
            }
            if ((tid & 31) == 0) wk[rg * 4 + r][(tid >> 5) & 1] = key;
        }
        __syncthreads();
        if (tid < FIXROWS) {
            int fr = g * FIXROWS + tid;
            if (fr < n) {
                unsigned long long best = min(wk[tid][0], wk[tid][1]);
                atomicMin(&g_fbest[g_fixrows[fr]], best);
            }
        }
    }
}

// ===== launch #7: apply fixups + gather codes =====
__global__ void gather_kernel(const float* __restrict__ cb, float* __restrict__ out) {
    __shared__ int s_idx[4];
    int tid = threadIdx.x;
    int rslot = tid >> 6;
    int row = blockIdx.x * 4 + rslot;
    int c = tid & 63;
    if (c == 0) {
        int idx;
        if (g_isfix[row]) {
            unsigned long long best = g_fbest[row];
            idx = (int)(uint32_t)best;
            out[IDX_OFF + row]  = (float)idx;
            out[DIST_OFF + row] = g_xsq[row] + decf((uint32_t)(best >> 32));
        } else {
            idx = g_idx[row];
        }
        s_idx[rslot] = idx;
    }
    __syncthreads();
    int idx = s_idx[rslot];
    reinterpret_cast<float4*>(out)[(size_t)row * 64 + c] =
        reinterpret_cast<const float4*>(cb)[(size_t)idx * 64 + c];
}

extern "C" void kernel_launch(void* const* d_in, const int* in_sizes, int n_in,
                              void* d_out, int out_size) {
    const float* x  = (const float*)d_in[0];   // z_e_x  [8,4096,256] f32
    const float* cb = (const float*)d_in[1];   // codebook [8192,256] f32
    float* out = (float*)d_out;                // codes | idx | distances (f32)

    cudaFuncSetAttribute(vq_hmma_kernel,
                         cudaFuncAttributeMaxDynamicSharedMemorySize, SMEM_TOTAL);

    init_kernel<<<RTOT / 256, 256>>>();                    // #1
    prep_a_kernel<<<(RTOT * 32) / 256, 256>>>(x);          // #2 (+ xsq fused)
    prep_b_kernel<<<(KTOT * 32) / 256, 256>>>(cb);         // #3 (+ cbsq fused)
    vq_hmma_kernel<<<NCTA, THREADS, SMEM_TOTAL>>>();       // #4  <- ncu capture slot
    final_kernel<<<RTOT / 256, 256>>>(out);                // #5
    fixup_kernel<<<NCTA * KSLICES, 256>>>(x, cb);          // #6 (8-way K-sliced)
    gather_kernel<<<RTOT / 4, 256>>>(cb, out);             // #7 (apply + gather)
}

// round 11
// speedup vs baseline: 5.7400x; 1.0097x over previous
#include <cuda_runtime.h>
#include <cuda_fp16.h>
#include <cstdint>

// ===== problem constants =====
#define RTOT  32768
#define CDIM  256
#define KTOT  8192
#define MT    128
#define NT    64               // narrower N-tile: 32KB B stages
#define KSTEPS 16
#define NUM_MT (RTOT/MT)       // 256
#define NUM_NT (KTOT/NT)       // 128
#define JOBS  (NUM_MT*NUM_NT)  // 32768
#define NCTA  148
#define THREADS 256

#define SMEM_A    0
#define SMEM_B    65536        // 4 stages x 32KB
#define SMEM_BAR  196608       // 8 mbarriers (full[4], empty[4])
#define SMEM_TOTAL 196736

#define IDX_OFF  8388608
#define DIST_OFF (8388608+32768)

#define VOFF 1024.0f
#define MARGIN 0.09f
#define FIXROWS 16
#define KSLICES 8

// ===== device globals (static scratch) =====
__device__ uint4 g_Aimg[(size_t)NUM_MT*4096];   // [mtile][panel16][256 u16x8] swizzled hi-fp16
__device__ uint4 g_Bimg[(size_t)NUM_NT*2048];   // [ntile64][panel16][128 units] swizzled hi-fp16
__device__ float g_cbsq[KTOT];
__device__ float g_cbsqo[KTOT];
__device__ float g_xsq[RTOT];
__device__ int   g_idx[RTOT];
__device__ unsigned long long g_best[RTOT];
__device__ unsigned int g_best2[RTOT];
__device__ int g_fixcnt;
__device__ int g_fixrows[RTOT];
__device__ int g_isfix[RTOT];
__device__ unsigned long long g_fbest[RTOT];

// ===== helpers =====
__device__ __forceinline__ uint32_t smem_u32(const void* p) {
    uint32_t a;
    asm("{ .reg .u64 t; cvta.to.shared.u64 t, %1; cvt.u32.u64 %0, t; }" : "=r"(a) : "l"(p));
    return a;
}
__device__ __forceinline__ void cp_async16(uint32_t sa, const void* g) {
    asm volatile("cp.async.cg.shared.global [%0], [%1], 16;" :: "r"(sa), "l"(g));
}
#define CP_COMMIT() asm volatile("cp.async.commit_group;" ::: "memory")
#define CP_WAIT(N)  asm volatile("cp.async.wait_group %0;" :: "n"(N) : "memory")

#define MBARRIER_INIT(mb, c) asm volatile("mbarrier.init.shared.b64 [%0], %1;" :: "r"((uint32_t)(mb)), "r"((uint32_t)(c)) : "memory")
#define MBARRIER_ARRIVE(mb)  asm volatile("mbarrier.arrive.shared.b64 _, [%0];" :: "r"((uint32_t)(mb)) : "memory")
#define CP_ASYNC_MBAR_ARRIVE(mb) asm volatile("cp.async.mbarrier.arrive.noinc.shared.b64 [%0];" :: "r"((uint32_t)(mb)) : "memory")

#define MBAR_WAIT(mb, par) do {                                                   \
    uint32_t _m = (uint32_t)(mb), _p = (uint32_t)(par), _d;                       \
    asm volatile("{\n\t.reg .pred p;\n\t"                                         \
        "mbarrier.try_wait.parity.acquire.cta.shared::cta.b64 p, [%1], %2;\n\t"   \
        "selp.b32 %0,1,0,p;\n\t}" : "=r"(_d) : "r"(_m), "r"(_p) : "memory");      \
    if (!_d) {                                                                    \
        asm volatile("{\n\t.reg .pred P1;\n\t"                                    \
        "WL_%=:\n\t"                                                              \
        "mbarrier.try_wait.parity.acquire.cta.shared::cta.b64 P1, [%0], %1, 0x989680;\n\t" \
        "@P1 bra.uni WD_%=;\n\t"                                                  \
        "bra.uni WL_%=;\n\t"                                                      \
        "WD_%=:\n\t}" :: "r"(_m), "r"(_p) : "memory");                            \
    }                                                                             \
} while (0)

__device__ __forceinline__ void ldsm4(uint32_t* r, uint32_t addr) {
    asm volatile("ldmatrix.sync.aligned.m8n8.x4.shared.b16 {%0,%1,%2,%3}, [%4];"
        : "=r"(r[0]), "=r"(r[1]), "=r"(r[2]), "=r"(r[3]) : "r"(addr));
}
__device__ __forceinline__ void mma16816(float* c, const uint32_t* a, uint32_t b0, uint32_t b1) {
    asm volatile("mma.sync.aligned.m16n8k16.row.col.f32.f16.f16.f32 "
        "{%0,%1,%2,%3}, {%4,%5,%6,%7}, {%8,%9}, {%0,%1,%2,%3};"
        : "+f"(c[0]), "+f"(c[1]), "+f"(c[2]), "+f"(c[3])
        : "r"(a[0]), "r"(a[1]), "r"(a[2]), "r"(a[3]), "r"(b0), "r"(b1));
}
__device__ __forceinline__ uint32_t encf(float f) {
    uint32_t u = __float_as_uint(f);
    return (u & 0x80000000u) ? ~u : (u | 0x80000000u);
}
__device__ __forceinline__ float decf(uint32_t e) {
    uint32_t u = (e & 0x80000000u) ? (e & 0x7fffffffu) : ~e;
    return __uint_as_float(u);
}
__device__ __forceinline__ uint32_t packh2(__half a, __half b) {
    __half2 h = __halves2half2(a, b);
    return *reinterpret_cast<uint32_t*>(&h);
}

// ===== launch #1: init =====
__global__ void init_kernel() {
    int i = blockIdx.x * 256 + threadIdx.x;
    g_best[i] = ~0ull;
    g_best2[i] = 0xFFFFFFFFu;
    g_isfix[i] = 0;
    g_fbest[i] = ~0ull;
    if (i == 0) g_fixcnt = 0;
}

// ===== launches #2/#3: prep (swizzled fp16 image + fused row sumsq) =====
__global__ void prep_a_kernel(const float* __restrict__ x) {
    int t = blockIdx.x * 256 + threadIdx.x;
    int row = t >> 5, u = t & 31;
    int ks = u >> 1, kh = u & 1;
    const float* r = x + (size_t)row * CDIM + ks * 16 + kh * 8;
    float s = 0.f;
    __half h[8];
#pragma unroll
    for (int i = 0; i < 8; ++i) { float v = r[i]; s = fmaf(v, v, s); h[i] = __float2half(v); }
    uint4 val;
    val.x = packh2(h[0], h[1]); val.y = packh2(h[2], h[3]);
    val.z = packh2(h[4], h[5]); val.w = packh2(h[6], h[7]);
    int tile = row >> 7, rl = row & 127;
    int phys = (rl * 2 + kh) ^ ((rl >> 2) & 1);
    g_Aimg[(size_t)tile * 4096 + ks * 256 + phys] = val;
#pragma unroll
    for (int o = 16; o; o >>= 1) s += __shfl_xor_sync(0xffffffffu, s, o);
    if ((t & 31) == 0) g_xsq[row] = s;
}
__global__ void prep_b_kernel(const float* __restrict__ cb) {
    int t = blockIdx.x * 256 + threadIdx.x;
    int row = t >> 5, u = t & 31;
    int ks = u >> 1, kh = u & 1;
    const float* r = cb + (size_t)row * CDIM + ks * 16 + kh * 8;
    float s = 0.f;
    __half h[8];
#pragma unroll
    for (int i = 0; i < 8; ++i) { float v = r[i]; s = fmaf(v, v, s); h[i] = __float2half(v); }
    uint4 val;
    val.x = packh2(h[0], h[1]); val.y = packh2(h[2], h[3]);
    val.z = packh2(h[4], h[5]); val.w = packh2(h[6], h[7]);
    int nt = row >> 6, rl = row & 63;
    int phys = (rl * 2 + kh) ^ ((rl >> 2) & 1);
    g_Bimg[(size_t)nt * 2048 + ks * 128 + phys] = val;
#pragma unroll
    for (int o = 16; o; o >>= 1) s += __shfl_xor_sync(0xffffffffu, s, o);
    if ((t & 31) == 0) { g_cbsq[row] = s; g_cbsqo[row] = s + VOFF; }
}

// ===== launch #4: main HMMA kernel, mbarrier-pipelined B =====
__device__ __forceinline__ void issue_A(uint32_t smemA, int m, int tid) {
    const uint4* src = g_Aimg + (size_t)m * 4096 + tid;
#pragma unroll
    for (int i = 0; i < 16; ++i)
        cp_async16(smemA + (tid + i * 256) * 16, src + i * 256);
}
// produce B stage for job-index jpi (job j): wait empty, fill slice, noinc-arrive full
__device__ __forceinline__ void produce_stage(uint32_t smB, uint32_t bar, int jpi, int j, int tid) {
    int sp = jpi & 3;
    int par = (((jpi >> 2) & 1) ^ 1);
    MBAR_WAIT(bar + 32 + sp * 8, par);             // empty[sp]
    const uint4* src = g_Bimg + (size_t)(j & (NUM_NT - 1)) * 2048 + tid;
    uint32_t dst = smB + sp * 32768 + tid * 16;
#pragma unroll
    for (int i = 0; i < 8; ++i)
        cp_async16(dst + i * 4096, src + i * 256);
    CP_ASYNC_MBAR_ARRIVE(bar + sp * 8);            // full[sp] on completion
}

__global__ __launch_bounds__(THREADS, 1)
void vq_hmma_kernel() {
    extern __shared__ char smem[];
    uint32_t sb = smem_u32(smem);
    uint32_t smA = sb + SMEM_A;
    uint32_t smB = sb + SMEM_B;
    uint32_t bar = sb + SMEM_BAR;

    int tid = threadIdx.x;
    int l = tid & 31, w = tid >> 5;
    int wm = w >> 1, wn = w & 1;     // wm: 4 row-slices of 32; wn: 2 col-halves of 32

    uint32_t aoff[2], boff[2];
#pragma unroll
    for (int mt = 0; mt < 2; ++mt) {
        int row = wm * 32 + mt * 16 + (l & 15);
        int kh = l >> 4;
        aoff[mt] = (uint32_t)(((row * 2 + kh) ^ ((row >> 2) & 1)) << 4);
    }
#pragma unroll
    for (int g = 0; g < 2; ++g) {
        int code = wn * 32 + g * 16 + (l & 7) + ((l >> 4) << 3);
        int kh = (l >> 3) & 1;
        boff[g] = (uint32_t)(((code * 2 + kh) ^ ((code >> 2) & 1)) << 4);
    }

    int start = (int)(((long long)blockIdx.x * JOBS) / NCTA);
    int end   = (int)(((long long)(blockIdx.x + 1) * JOBS) / NCTA);
    int njobs = end - start;

    if (tid == 0) {
#pragma unroll
        for (int s = 0; s < 4; ++s) {
            MBARRIER_INIT(bar + s * 8, 256);        // full
            MBARRIER_INIT(bar + 32 + s * 8, 256);   // empty
        }
    }
    __syncthreads();

    int cur_m = start >> 7;
    issue_A(smA, cur_m, tid); CP_COMMIT();
#pragma unroll
    for (int p = 0; p < 3; ++p)
        if (p < njobs) produce_stage(smB, bar, p, start + p, tid);
    CP_WAIT(0);                 // A group (B stage copies are mbarrier-tracked)
    __syncthreads();            // A visible block-wide

    float rb[2][2] = {{3.4e38f,3.4e38f},{3.4e38f,3.4e38f}};
    float rs[2][2] = {{3.4e38f,3.4e38f},{3.4e38f,3.4e38f}};
    int   ri[2][2] = {{0,0},{0,0}};

    for (int ji = 0; ji < njobs; ++ji) {
        int j = start + ji;
        int ntj = j & (NUM_NT - 1);
        int s = ji & 3;

        MBAR_WAIT(bar + s * 8, (ji >> 2) & 1);      // full[s]

        float qv[8];
        int qbase = ntj * NT + wn * 32 + (l & 3) * 2;
#pragma unroll
        for (int nb = 0; nb < 4; ++nb) {
            qv[nb * 2]     = __ldg(&g_cbsqo[qbase + nb * 8]);
            qv[nb * 2 + 1] = __ldg(&g_cbsqo[qbase + nb * 8 + 1]);
        }

        float acc[2][4][4];
#pragma unroll
        for (int mt = 0; mt < 2; ++mt)
#pragma unroll
            for (int nb = 0; nb < 4; ++nb)
#pragma unroll
                for (int q = 0; q < 4; ++q) acc[mt][nb][q] = 0.f;

        uint32_t Bstage = smB + s * 32768;
#pragma unroll
        for (int ks = 0; ks < KSTEPS; ++ks) {
            uint32_t Apan = smA + ks * 4096;
            uint32_t Bpan = Bstage + ks * 2048;
            uint32_t af[2][4], bf[2][4];
            ldsm4(af[0], Apan + aoff[0]);
            ldsm4(af[1], Apan + aoff[1]);
            ldsm4(bf[0], Bpan + boff[0]);
            ldsm4(bf[1], Bpan + boff[1]);
#pragma unroll
            for (int mt = 0; mt < 2; ++mt)
#pragma unroll
                for (int g = 0; g < 2; ++g) {
                    mma16816(acc[mt][g*2  ], af[mt], bf[g][0], bf[g][1]);
                    mma16816(acc[mt][g*2+1], af[mt], bf[g][2], bf[g][3]);
                }
        }

        MBARRIER_ARRIVE(bar + 32 + s * 8);          // empty[s]: this thread done reading

        // epilogue (registers only) — overlaps other warps' MMAs via skew
#pragma unroll
        for (int mt = 0; mt < 2; ++mt)
#pragma unroll
            for (int h = 0; h < 2; ++h) {
                uint32_t k1 = 0xFFFFFFFFu, k2 = 0xFFFFFFFFu;
#pragma unroll
                for (int nb = 0; nb < 4; ++nb)
#pragma unroll
                    for (int c = 0; c < 2; ++c) {
                        float v = fmaf(-2.f, acc[mt][nb][h * 2 + c], qv[nb * 2 + c]);
                        uint32_t k = (__float_as_uint(v) & 0xFFFFFFF8u) | (uint32_t)(nb * 2 + c);
                        uint32_t t = max(k1, k);
                        k1 = min(k1, k);
                        k2 = min(k2, t);
                    }
                float v1 = __uint_as_float(k1 & 0xFFFFFFF8u);
                float v2 = __uint_as_float(k2 & 0xFFFFFFF8u);
                int li = (int)(k1 & 7u);
                int gidx = qbase + (li >> 1) * 8 + (li & 1);
                if (v1 < rb[mt][h]) {
                    rs[mt][h] = fminf(rb[mt][h], v2);
                    rb[mt][h] = v1; ri[mt][h] = gidx;
                } else {
                    rs[mt][h] = fminf(rs[mt][h], v1);
                }
            }

        int jn = j + 1;
        bool m_change = (jn < end) && ((jn >> 7) != cur_m);
        if (m_change || jn == end) {
#pragma unroll
            for (int mt = 0; mt < 2; ++mt)
#pragma unroll
                for (int h = 0; h < 2; ++h) {
                    float bv = rb[mt][h], sv = rs[mt][h];
                    int bi = ri[mt][h];
#pragma unroll
                    for (int o = 1; o < 4; o <<= 1) {
                        float ov = __shfl_xor_sync(0xffffffffu, bv, o);
                        int   oi = __shfl_xor_sync(0xffffffffu, bi, o);
                        float os = __shfl_xor_sync(0xffffffffu, sv, o);
                        if (ov < bv || (ov == bv && oi < bi)) {
                            sv = fminf(bv, os); bv = ov; bi = oi;
                        } else {
                            sv = fminf(sv, ov);
                        }
                    }
                    if ((l & 3) == 0) {
                        int r = cur_m * MT + wm * 32 + mt * 16 + h * 8 + (l >> 2);
                        unsigned long long key =
                            ((unsigned long long)encf(bv) << 32) | (uint32_t)bi;
                        unsigned long long old = atomicMin(&g_best[r], key);
                        uint32_t oldenc = (uint32_t)(old >> 32);
                        uint32_t be = encf(bv);
                        uint32_t cand = min(encf(sv), max(be, oldenc));
                        atomicMin(&g_best2[r], cand);
                    }
                    rb[mt][h] = 3.4e38f; rs[mt][h] = 3.4e38f; ri[mt][h] = 0;
                }
        }

        if (ji + 3 < njobs) produce_stage(smB, bar, ji + 3, start + ji + 3, tid);

        if (m_change) {
            cur_m = jn >> 7;
            __syncthreads();                        // all warps done reading smA
            issue_A(smA, cur_m, tid); CP_COMMIT();
            CP_WAIT(0);
            __syncthreads();                        // new A visible
        }
    }
}

// ===== launch #5: finalize, flag close rows =====
__global__ void final_kernel(float* __restrict__ out) {
    int i = blockIdx.x * 256 + threadIdx.x;
    unsigned long long key = g_best[i];
    int idx = (int)(uint32_t)key;
    float val = decf((uint32_t)(key >> 32)) - VOFF;
    float sec = decf(g_best2[i]) - VOFF;
    out[IDX_OFF + i]  = (float)idx;
    out[DIST_OFF + i] = g_xsq[i] + val;
    g_idx[i] = idx;
    if (sec - val < MARGIN) {
        g_isfix[i] = 1;
        int p = atomicAdd(&g_fixcnt, 1);
        g_fixrows[p] = i;
    }
}

// ===== launch #6: exact fp32 rescan, K-sliced 8-way =====
__global__ __launch_bounds__(256) void fixup_kernel(const float* __restrict__ x,
                                                    const float* __restrict__ cb) {
    __shared__ float4 xs[FIXROWS][64];
    __shared__ unsigned long long wk[FIXROWS][2];
    int tid = threadIdx.x;
    int n = g_fixcnt;
    int ngroups = (n + FIXROWS - 1) / FIXROWS;
    int slice = blockIdx.x & (KSLICES - 1);
    int g0 = blockIdx.x >> 3;
    const float4* c4 = reinterpret_cast<const float4*>(cb);
    for (int g = g0; g < ngroups; g += NCTA) {
        __syncthreads();
        for (int i = tid; i < FIXROWS * 64; i += 256) {
            int r = i >> 6, q = i & 63;
            int fr = g * FIXROWS + r;
            int row = g_fixrows[(fr < n) ? fr : g * FIXROWS];
            xs[r][q] = reinterpret_cast<const float4*>(x)[(size_t)row * 64 + q];
        }
        __syncthreads();
        int rg = tid >> 6;
        int cg = tid & 63;
        float bv[4] = {3.4e38f,3.4e38f,3.4e38f,3.4e38f};
        int   bi[4] = {0,0,0,0};
        for (int k = slice * 4; k < slice * 4 + 4; ++k) {
            int c0 = k * 256 + cg * 4;
            float acc[4][4];
#pragma unroll
            for (int r = 0; r < 4; ++r)
#pragma unroll
                for (int cc = 0; cc < 4; ++cc) acc[r][cc] = 0.f;
#pragma unroll 8
            for (int q = 0; q < 64; ++q) {
                float4 xv[4];
#pragma unroll
                for (int r = 0; r < 4; ++r) xv[r] = xs[rg * 4 + r][q];
#pragma unroll
                for (int cc = 0; cc < 4; ++cc) {
                    float4 v = c4[(size_t)(c0 + cc) * 64 + q];
#pragma unroll
                    for (int r = 0; r < 4; ++r) {
                        acc[r][cc] = fmaf(v.x, xv[r].x, acc[r][cc]);
                        acc[r][cc] = fmaf(v.y, xv[r].y, acc[r][cc]);
                        acc[r][cc] = fmaf(v.z, xv[r].z, acc[r][cc]);
                        acc[r][cc] = fmaf(v.w, xv[r].w, acc[r][cc]);
                    }
                }
            }
#pragma unroll
            for (int cc = 0; cc < 4; ++cc) {
                float cq = __ldg(&g_cbsq[c0 + cc]);
#pragma unroll
                for (int r = 0; r < 4; ++r) {
                    float val = fmaf(-2.f, acc[r][cc], cq);
                    if (val < bv[r] || (val == bv[r] && c0 + cc < bi[r])) {
                        bv[r] = val; bi[r] = c0 + cc;
                    }
                }
            }
        }
#pragma unroll
        for (int r = 0; r < 4; ++r) {
            unsigned long long key =
                ((unsigned long long)encf(bv[r]) << 32) | (uint32_t)bi[r];
#pragma unroll
            for (int o = 16; o; o >>= 1) {
                unsigned long long ok = __shfl_xor_sync(0xffffffffu, key, o);
                key = min(key, ok);
            }
            if ((tid & 31) == 0) wk[rg * 4 + r][(tid >> 5) & 1] = key;
        }
        __syncthreads();
        if (tid < FIXROWS) {
            int fr = g * FIXROWS + tid;
            if (fr < n) {
                unsigned long long best = min(wk[tid][0], wk[tid][1]);
                atomicMin(&g_fbest[g_fixrows[fr]], best);
            }
        }
    }
}

// ===== launch #7: apply fixups + gather codes =====
__global__ void gather_kernel(const float* __restrict__ cb, float* __restrict__ out) {
    __shared__ int s_idx[4];
    int tid = threadIdx.x;
    int rslot = tid >> 6;
    int row = blockIdx.x * 4 + rslot;
    int c = tid & 63;
    if (c == 0) {
        int idx;
        if (g_isfix[row]) {
            unsigned long long best = g_fbest[row];
            idx = (int)(uint32_t)best;
            out[IDX_OFF + row]  = (float)idx;
            out[DIST_OFF + row] = g_xsq[row] + decf((uint32_t)(best >> 32));
        } else {
            idx = g_idx[row];
        }
        s_idx[rslot] = idx;
    }
    __syncthreads();
    int idx = s_idx[rslot];
    reinterpret_cast<float4*>(out)[(size_t)row * 64 + c] =
        reinterpret_cast<const float4*>(cb)[(size_t)idx * 64 + c];
}

extern "C" void kernel_launch(void* const* d_in, const int* in_sizes, int n_in,
                              void* d_out, int out_size) {
    const float* x  = (const float*)d_in[0];   // z_e_x  [8,4096,256] f32
    const float* cb = (const float*)d_in[1];   // codebook [8192,256] f32
    float* out = (float*)d_out;                // codes | idx | distances (f32)

    cudaFuncSetAttribute(vq_hmma_kernel,
                         cudaFuncAttributeMaxDynamicSharedMemorySize, SMEM_TOTAL);

    init_kernel<<<RTOT / 256, 256>>>();                    // #1
    prep_a_kernel<<<(RTOT * 32) / 256, 256>>>(x);          // #2
    prep_b_kernel<<<(KTOT * 32) / 256, 256>>>(cb);         // #3
    vq_hmma_kernel<<<NCTA, THREADS, SMEM_TOTAL>>>();       // #4  <- ncu capture slot
    final_kernel<<<RTOT / 256, 256>>>(out);                // #5
    fixup_kernel<<<NCTA * KSLICES, 256>>>(x, cb);          // #6
    gather_kernel<<<RTOT / 4, 256>>>(cb, out);             // #7
}